// round 1
// baseline (speedup 1.0000x reference)
#include <cuda_runtime.h>
#include <cuda_bf16.h>

// Shapes
#define Bb 4
#define Ll 48
#define LP 96
#define Nn 512
#define Dd 128
#define DF 512
#define Hh 8
#define HD 16

#define M1 (Bb*Ll*Nn)    // 98304
#define M2 (Bb*LP*Nn)    // 196608
#define BLn (Bb*Ll)      // 192

// ---------------- scratch (static device memory; no allocations) ----------------
__device__ float g_q [M1*Dd];
__device__ float g_k [M2*Dd];
__device__ float g_v [M2*Dd];
__device__ float g_t [M1*Dd];
__device__ float g_h [M1*Dd];
__device__ float g_xn[M1*Dd];
__device__ float g_y [M1*Dd];
__device__ float g_big[(long long)M1*DF];          // y1 then A
__device__ float g_Hb[(long long)BLn*640*Nn];      // Hc: [192][640][512]
__device__ float g_go[(long long)BLn*Dd*Nn];       // gout: [192][128][512]

// ---------------- generic fp32 GEMM: C = A@B (+bias)(+relu), batched ----------------
// A[M,K] row-major (lda=K), B[K,N] (ldb=N), C[M,N] (ldc=N).
// Per batch z: A += (modA? z%modA : z)*sA ; B += z*sB ; C += z*sC.
__global__ void __launch_bounds__(256) sgemm_kernel(
    const float* __restrict__ A, const float* __restrict__ B, float* __restrict__ C,
    int M, int N, int K,
    long long sA, long long sB, long long sC, int modA,
    const float* __restrict__ bias, int doRelu)
{
    __shared__ float As[8][128];
    __shared__ float Bs[8][128];

    int z = blockIdx.z;
    const float* Ap = A + (long long)(modA > 0 ? (z % modA) : z) * sA;
    const float* Bp = B + (long long)z * sB;
    float*       Cp = C + (long long)z * sC;

    int tid  = threadIdx.x;
    int brow = blockIdx.y * 128;
    int bcol = blockIdx.x * 128;

    int aRow = tid >> 1;        // 0..127
    int aCol = (tid & 1) * 4;   // 0 or 4
    int bRow = tid >> 5;        // 0..7
    int bCol = (tid & 31) * 4;  // 0..124

    const float* aPtr = Ap + (long long)(brow + aRow) * K + aCol;
    const float* bPtr = Bp + (long long)bRow * N + bcol + bCol;

    int tx = tid & 15, ty = tid >> 4;
    float acc[8][8];
    #pragma unroll
    for (int i = 0; i < 8; i++)
        #pragma unroll
        for (int j = 0; j < 8; j++) acc[i][j] = 0.f;

    for (int k0 = 0; k0 < K; k0 += 8) {
        float4 a4 = *(const float4*)aPtr;
        As[aCol+0][aRow] = a4.x;
        As[aCol+1][aRow] = a4.y;
        As[aCol+2][aRow] = a4.z;
        As[aCol+3][aRow] = a4.w;
        *(float4*)&Bs[bRow][bCol] = *(const float4*)bPtr;
        __syncthreads();

        #pragma unroll
        for (int kk = 0; kk < 8; kk++) {
            float4 ra0 = *(const float4*)&As[kk][ty*8];
            float4 ra1 = *(const float4*)&As[kk][ty*8+4];
            float4 rb0 = *(const float4*)&Bs[kk][tx*8];
            float4 rb1 = *(const float4*)&Bs[kk][tx*8+4];
            float ra[8] = {ra0.x,ra0.y,ra0.z,ra0.w,ra1.x,ra1.y,ra1.z,ra1.w};
            float rb[8] = {rb0.x,rb0.y,rb0.z,rb0.w,rb1.x,rb1.y,rb1.z,rb1.w};
            #pragma unroll
            for (int i = 0; i < 8; i++)
                #pragma unroll
                for (int j = 0; j < 8; j++)
                    acc[i][j] = fmaf(ra[i], rb[j], acc[i][j]);
        }
        __syncthreads();
        aPtr += 8;
        bPtr += 8LL * N;
    }

    #pragma unroll
    for (int i = 0; i < 8; i++) {
        int row = brow + ty*8 + i;
        #pragma unroll
        for (int j = 0; j < 8; j++) {
            float vv = acc[i][j];
            if (bias)   vv += bias[bcol + tx*8 + j];
            if (doRelu) vv = fmaxf(vv, 0.f);
            acc[i][j] = vv;
        }
        float* cp = Cp + (long long)row * N + bcol + tx*8;
        *(float4*)cp       = make_float4(acc[i][0], acc[i][1], acc[i][2], acc[i][3]);
        *(float4*)(cp + 4) = make_float4(acc[i][4], acc[i][5], acc[i][6], acc[i][7]);
    }
}

// ---------------- attention: one block per (b, n, h) ----------------
// Q [B,Lq,N,D], K/V [B,Lk,N,D]; head h = cols h*16..h*16+15. Softmax over Lk.
__global__ void __launch_bounds__(128) attn_kernel(
    const float* __restrict__ Q, const float* __restrict__ Kt, const float* __restrict__ V,
    float* __restrict__ O, int Lq, int Lk)
{
    __shared__ float Qs[48*16];
    __shared__ float Ks[96*16];
    __shared__ float Vs[96*16];
    __shared__ float Ss[48*96];

    int bid = blockIdx.x;
    int h = bid & 7;
    int n = (bid >> 3) & (Nn - 1);
    int b = bid >> 12;           // /(8*512)
    int tid = threadIdx.x;

    for (int i = tid; i < Lq*16; i += 128) {
        int l = i >> 4, j = i & 15;
        Qs[i] = Q[(((long long)(b*Lq + l))*Nn + n)*Dd + h*HD + j];
    }
    for (int i = tid; i < Lk*16; i += 128) {
        int m = i >> 4, j = i & 15;
        long long base = (((long long)(b*Lk + m))*Nn + n)*Dd + h*HD + j;
        Ks[i] = Kt[base];
        Vs[i] = V[base];
    }
    __syncthreads();

    const float scale = 0.25f;  // 1/sqrt(16)
    for (int i = tid; i < Lq*Lk; i += 128) {
        int l = i / Lk, m = i - l*Lk;
        float s = 0.f;
        #pragma unroll
        for (int j = 0; j < 16; j++) s = fmaf(Qs[l*16+j], Ks[m*16+j], s);
        Ss[l*Lk + m] = s * scale;
    }
    __syncthreads();

    if (tid < Lq) {
        float mx = -1e30f;
        for (int m = 0; m < Lk; m++) mx = fmaxf(mx, Ss[tid*Lk+m]);
        float sum = 0.f;
        for (int m = 0; m < Lk; m++) {
            float e = __expf(Ss[tid*Lk+m] - mx);
            Ss[tid*Lk+m] = e;
            sum += e;
        }
        float inv = 1.f / sum;
        for (int m = 0; m < Lk; m++) Ss[tid*Lk+m] *= inv;
    }
    __syncthreads();

    for (int i = tid; i < Lq*16; i += 128) {
        int l = i >> 4, j = i & 15;
        float a = 0.f;
        for (int m = 0; m < Lk; m++) a = fmaf(Ss[l*Lk+m], Vs[m*16+j], a);
        O[(((long long)(b*Lq + l))*Nn + n)*Dd + h*HD + j] = a;
    }
}

// ---------------- fused residual add + LayerNorm (1 warp per 128-elem row) ----------------
__global__ void __launch_bounds__(256) ln_add_kernel(
    float* __restrict__ out, const float* __restrict__ X, const float* __restrict__ P,
    const float* __restrict__ g, const float* __restrict__ bta, int rows)
{
    int row  = (blockIdx.x * 256 + threadIdx.x) >> 5;
    int lane = threadIdx.x & 31;
    if (row >= rows) return;
    long long base = (long long)row * Dd + lane*4;
    float4 a = *(const float4*)(X + base);
    float4 p = *(const float4*)(P + base);
    float v0 = a.x+p.x, v1 = a.y+p.y, v2 = a.z+p.z, v3 = a.w+p.w;
    float s  = v0+v1+v2+v3;
    float s2 = v0*v0+v1*v1+v2*v2+v3*v3;
    #pragma unroll
    for (int o = 16; o; o >>= 1) {
        s  += __shfl_xor_sync(0xffffffffu, s,  o);
        s2 += __shfl_xor_sync(0xffffffffu, s2, o);
    }
    float mu  = s * (1.f/128.f);
    float var = s2 * (1.f/128.f) - mu*mu;
    float rs  = rsqrtf(var + 1e-5f);
    float4 gg = *(const float4*)(g   + lane*4);
    float4 bb = *(const float4*)(bta + lane*4);
    float4 o4;
    o4.x = (v0-mu)*rs*gg.x + bb.x;
    o4.y = (v1-mu)*rs*gg.y + bb.y;
    o4.z = (v2-mu)*rs*gg.z + bb.z;
    o4.w = (v3-mu)*rs*gg.w + bb.w;
    *(float4*)(out + base) = o4;
}

// ---------------- transpose data[b,l] ([512,128]) -> g0 rows of Hc ([128,512]) ----------------
__global__ void transpose_g0_kernel(const float* __restrict__ in, float* __restrict__ out)
{
    __shared__ float t[32][33];
    int bl = blockIdx.z;
    int n0 = blockIdx.x * 32;
    int c0 = blockIdx.y * 32;
    const float* ip = in  + (long long)bl * (Nn*Dd);
    float*       op = out + (long long)bl * (640*Nn);
    #pragma unroll
    for (int j = 0; j < 32; j += 8)
        t[threadIdx.y + j][threadIdx.x] = ip[(n0 + threadIdx.y + j)*Dd + c0 + threadIdx.x];
    __syncthreads();
    #pragma unroll
    for (int j = 0; j < 32; j += 8)
        op[(c0 + threadIdx.y + j)*Nn + n0 + threadIdx.x] = t[threadIdx.x][threadIdx.y + j];
}

// ---------------- transpose gout[bl] ([128,512]) + gcn_b -> dts ([512,128]) ----------------
__global__ void transpose_gout_kernel(const float* __restrict__ in, const float* __restrict__ gb,
                                      float* __restrict__ out)
{
    __shared__ float t[32][33];
    int bl = blockIdx.z;
    int l  = bl % Ll;
    int n0 = blockIdx.x * 32;
    int o0 = blockIdx.y * 32;
    const float* ip = in  + (long long)bl * (Dd*Nn);
    float*       op = out + (long long)bl * (Nn*Dd);
    #pragma unroll
    for (int j = 0; j < 32; j += 8)
        t[threadIdx.y + j][threadIdx.x] = ip[(o0 + threadIdx.y + j)*Nn + n0 + threadIdx.x];
    __syncthreads();
    #pragma unroll
    for (int j = 0; j < 32; j += 8) {
        int o = o0 + threadIdx.x;
        op[(n0 + threadIdx.y + j)*Dd + o] = t[threadIdx.x][threadIdx.y + j] + gb[l*Dd + o];
    }
}

// ---------------- host ----------------
static inline void gemm(const float* A, const float* B, float* C, int M, int N, int K,
                        long long sA, long long sB, long long sC, int batch, int modA,
                        const float* bias, int relu)
{
    dim3 grid(N/128, M/128, batch);
    sgemm_kernel<<<grid, 256>>>(A, B, C, M, N, K, sA, sB, sC, modA, bias, relu);
}

extern "C" void kernel_launch(void* const* d_in, const int* in_sizes, int n_in,
                              void* d_out, int out_size)
{
    const float* x       = (const float*)d_in[0];
    const float* memory  = (const float*)d_in[1];
    const float* data    = (const float*)d_in[2];
    const float* support = (const float*)d_in[3];
    const float* Wq_s = (const float*)d_in[4];
    const float* Wk_s = (const float*)d_in[5];
    const float* Wv_s = (const float*)d_in[6];
    const float* Wo_s = (const float*)d_in[7];
    const float* Wq_c = (const float*)d_in[8];
    const float* Wk_c = (const float*)d_in[9];
    const float* Wv_c = (const float*)d_in[10];
    const float* Wo_c = (const float*)d_in[11];
    const float* W1   = (const float*)d_in[12];
    const float* b1   = (const float*)d_in[13];
    const float* W2   = (const float*)d_in[14];
    const float* b2   = (const float*)d_in[15];
    const float* W3   = (const float*)d_in[16];
    const float* b3   = (const float*)d_in[17];
    const float* gcnW = (const float*)d_in[18];
    const float* gcnB = (const float*)d_in[19];
    const float* ln1g = (const float*)d_in[20];
    const float* ln1b = (const float*)d_in[21];
    const float* ln2g = (const float*)d_in[22];
    const float* ln2b = (const float*)d_in[23];
    const float* ln3g = (const float*)d_in[24];
    const float* ln3b = (const float*)d_in[25];

    float *q, *k, *v, *t, *h, *xn, *y, *big, *Hb, *go;
    cudaGetSymbolAddress((void**)&q,  g_q);
    cudaGetSymbolAddress((void**)&k,  g_k);
    cudaGetSymbolAddress((void**)&v,  g_v);
    cudaGetSymbolAddress((void**)&t,  g_t);
    cudaGetSymbolAddress((void**)&h,  g_h);
    cudaGetSymbolAddress((void**)&xn, g_xn);
    cudaGetSymbolAddress((void**)&y,  g_y);
    cudaGetSymbolAddress((void**)&big, g_big);
    cudaGetSymbolAddress((void**)&Hb, g_Hb);
    cudaGetSymbolAddress((void**)&go, g_go);

    float* out1 = (float*)d_out;               // LN3(xn + y)
    float* out2 = out1 + (long long)M1 * Dd;   // dts

    const int nLnBlocks = M1 / 8;              // 8 rows per 256-thr block

    // ---- self-attention ----
    gemm(x, Wq_s, q, M1, Dd, Dd, 0,0,0, 1,0, nullptr, 0);
    gemm(x, Wk_s, k, M1, Dd, Dd, 0,0,0, 1,0, nullptr, 0);
    gemm(x, Wv_s, v, M1, Dd, Dd, 0,0,0, 1,0, nullptr, 0);
    attn_kernel<<<Bb*Nn*Hh, 128>>>(q, k, v, t, Ll, Ll);
    gemm(t, Wo_s, q, M1, Dd, Dd, 0,0,0, 1,0, nullptr, 0);
    ln_add_kernel<<<nLnBlocks, 256>>>(h, x, q, ln1g, ln1b, M1);

    // ---- cross-attention ----
    gemm(h,      Wq_c, t, M1, Dd, Dd, 0,0,0, 1,0, nullptr, 0);
    gemm(memory, Wk_c, k, M2, Dd, Dd, 0,0,0, 1,0, nullptr, 0);
    gemm(memory, Wv_c, v, M2, Dd, Dd, 0,0,0, 1,0, nullptr, 0);
    attn_kernel<<<Bb*Nn*Hh, 128>>>(t, k, v, q, Ll, LP);
    gemm(q, Wo_c, t, M1, Dd, Dd, 0,0,0, 1,0, nullptr, 0);
    ln_add_kernel<<<nLnBlocks, 256>>>(xn, h, t, ln2g, ln2b, M1);

    // ---- FFN ----
    gemm(xn,  W1, big, M1, DF, Dd, 0,0,0, 1,0, b1, 1);   // relu(xn@W1+b1)
    gemm(big, W2, y,   M1, Dd, DF, 0,0,0, 1,0, b2, 0);   // y
    ln_add_kernel<<<nLnBlocks, 256>>>(out1, xn, y, ln3g, ln3b, M1);  // output 1

    // ---- dynamic adjacency A = y@W3 + b3  ([192][512][512] in g_big) ----
    gemm(y, W3, big, M1, Nn, Dd, 0,0,0, 1,0, b3, 0);

    // ---- GCN ----
    transpose_g0_kernel<<<dim3(16,4,BLn), dim3(32,8)>>>(data, Hb);   // g0 -> rows 0..127
    // s1 = g0@S         -> rows 128..255
    gemm(Hb,              support, Hb +  65536, 128, Nn, Nn, 327680LL, 0,        327680LL, BLn, 0, nullptr, 0);
    // d1 = g0@A[bl]     -> rows 384..511
    gemm(Hb,              big,     Hb + 196608, 128, Nn, Nn, 327680LL, 262144LL, 327680LL, BLn, 0, nullptr, 0);
    // s2 = s1@S         -> rows 256..383
    gemm(Hb +  65536,     support, Hb + 131072, 128, Nn, Nn, 327680LL, 0,        327680LL, BLn, 0, nullptr, 0);
    // d2 = d1@A[bl]     -> rows 512..639
    gemm(Hb + 196608,     big,     Hb + 262144, 128, Nn, Nn, 327680LL, 262144LL, 327680LL, BLn, 0, nullptr, 0);
    // gout[bl] = gcn_W[l] @ Hc[bl]   (K = 640)
    gemm(gcnW, Hb, go, 128, Nn, 5*Dd, 81920LL, 327680LL, 65536LL, BLn, Ll, nullptr, 0);
    // dts = gout^T + gcn_b  -> output 2
    transpose_gout_kernel<<<dim3(16,4,BLn), dim3(32,8)>>>(go, gcnB, out2);
}

// round 2
// speedup vs baseline: 2.4781x; 2.4781x over previous
#include <cuda_runtime.h>
#include <cuda_bf16.h>

// Shapes
#define Bb 4
#define Ll 48
#define LP 96
#define Nn 512
#define Dd 128
#define DF 512
#define Hh 8
#define HD 16

#define M1 (Bb*Ll*Nn)    // 98304
#define M2 (Bb*LP*Nn)    // 196608
#define BLn (Bb*Ll)      // 192

// ---------------- scratch (static device memory; no allocations) ----------------
__device__ float g_q [M1*Dd];
__device__ float g_k [M2*Dd];
__device__ float g_v [M2*Dd];
__device__ float g_t [M1*Dd];
__device__ float g_h [M1*Dd];
__device__ float g_xn[M1*Dd];
__device__ float g_y [M1*Dd];
__device__ float g_big[(long long)M1*DF];          // y1 then A
__device__ float g_Hb[(long long)BLn*640*Nn];      // Hc: [192][640][512]
__device__ float g_go[(long long)BLn*Dd*Nn];       // gout: [192][128][512]

__device__ __forceinline__ unsigned f2tf32(float x) {
    unsigned u;
    asm("cvt.rna.tf32.f32 %0, %1;" : "=r"(u) : "f"(x));
    return u;
}

// ---------------- TF32 tensor-core GEMM: C = A@B (+bias)(+relu), batched ----------------
// A[M,K] row-major, B[K,N] row-major, C[M,N]. 128x128 tile, k-step 16, 8 warps.
// Per batch z: A += (modA? z%modA : z)*sA ; B += z*sB ; C += z*sC.
__global__ void __launch_bounds__(256) sgemm_kernel(
    const float* __restrict__ A, const float* __restrict__ B, float* __restrict__ C,
    int M, int N, int K,
    long long sA, long long sB, long long sC, int modA,
    const float* __restrict__ bias, int doRelu)
{
    __shared__ float As[128][20];   // 16 k-cols used, padded to 20 (conflict-free frag loads)
    __shared__ float Bs[16][136];   // 128 n-cols used, padded to 136

    int z = blockIdx.z;
    const float* Ap = A + (long long)(modA > 0 ? (z % modA) : z) * sA;
    const float* Bp = B + (long long)z * sB;
    float*       Cp = C + (long long)z * sC;

    int tid  = threadIdx.x;
    int warp = tid >> 5;
    int lane = tid & 31;
    int wm = warp >> 2;   // 0..1  (64-row warp tile)
    int wn = warp & 3;    // 0..3  (32-col warp tile)
    int lr = lane >> 2;   // 0..7
    int lc = lane & 3;    // 0..3

    int brow = blockIdx.y * 128;
    int bcol = blockIdx.x * 128;

    float acc[4][4][4];
    #pragma unroll
    for (int i = 0; i < 4; i++)
        #pragma unroll
        for (int j = 0; j < 4; j++)
            #pragma unroll
            for (int r = 0; r < 4; r++) acc[i][j][r] = 0.f;

    for (int k0 = 0; k0 < K; k0 += 16) {
        // load A tile 128x16
        #pragma unroll
        for (int u = 0; u < 2; u++) {
            int idx = tid + u*256;          // 0..511
            int r = idx >> 2;               // 0..127
            int c = (idx & 3) * 4;          // 0,4,8,12
            float4 v = *(const float4*)(Ap + (long long)(brow + r)*K + k0 + c);
            As[r][c+0] = __uint_as_float(f2tf32(v.x));
            As[r][c+1] = __uint_as_float(f2tf32(v.y));
            As[r][c+2] = __uint_as_float(f2tf32(v.z));
            As[r][c+3] = __uint_as_float(f2tf32(v.w));
        }
        // load B tile 16x128
        #pragma unroll
        for (int u = 0; u < 2; u++) {
            int idx = tid + u*256;
            int r = idx >> 5;               // 0..15
            int c = (idx & 31) * 4;         // 0..124
            float4 v = *(const float4*)(Bp + (long long)(k0 + r)*N + bcol + c);
            Bs[r][c+0] = __uint_as_float(f2tf32(v.x));
            Bs[r][c+1] = __uint_as_float(f2tf32(v.y));
            Bs[r][c+2] = __uint_as_float(f2tf32(v.z));
            Bs[r][c+3] = __uint_as_float(f2tf32(v.w));
        }
        __syncthreads();

        #pragma unroll
        for (int kk = 0; kk < 16; kk += 8) {
            unsigned a[4][4], b[4][2];
            #pragma unroll
            for (int mf = 0; mf < 4; mf++) {
                int row = wm*64 + mf*16 + lr;
                a[mf][0] = __float_as_uint(As[row  ][kk + lc]);
                a[mf][1] = __float_as_uint(As[row+8][kk + lc]);
                a[mf][2] = __float_as_uint(As[row  ][kk + lc + 4]);
                a[mf][3] = __float_as_uint(As[row+8][kk + lc + 4]);
            }
            #pragma unroll
            for (int nf = 0; nf < 4; nf++) {
                int col = wn*32 + nf*8 + lr;
                b[nf][0] = __float_as_uint(Bs[kk + lc    ][col]);
                b[nf][1] = __float_as_uint(Bs[kk + lc + 4][col]);
            }
            #pragma unroll
            for (int mf = 0; mf < 4; mf++)
                #pragma unroll
                for (int nf = 0; nf < 4; nf++) {
                    asm volatile(
                        "mma.sync.aligned.m16n8k8.row.col.f32.tf32.tf32.f32 "
                        "{%0,%1,%2,%3}, {%4,%5,%6,%7}, {%8,%9}, {%0,%1,%2,%3};\n"
                        : "+f"(acc[mf][nf][0]), "+f"(acc[mf][nf][1]),
                          "+f"(acc[mf][nf][2]), "+f"(acc[mf][nf][3])
                        : "r"(a[mf][0]), "r"(a[mf][1]), "r"(a[mf][2]), "r"(a[mf][3]),
                          "r"(b[nf][0]), "r"(b[nf][1]));
                }
        }
        __syncthreads();
    }

    // epilogue
    #pragma unroll
    for (int mf = 0; mf < 4; mf++) {
        int row0 = brow + wm*64 + mf*16 + lr;
        #pragma unroll
        for (int nf = 0; nf < 4; nf++) {
            int col = bcol + wn*32 + nf*8 + lc*2;
            float bx = 0.f, by = 0.f;
            if (bias) { bx = bias[col]; by = bias[col+1]; }
            float v0 = acc[mf][nf][0] + bx;
            float v1 = acc[mf][nf][1] + by;
            float v2 = acc[mf][nf][2] + bx;
            float v3 = acc[mf][nf][3] + by;
            if (doRelu) {
                v0 = fmaxf(v0, 0.f); v1 = fmaxf(v1, 0.f);
                v2 = fmaxf(v2, 0.f); v3 = fmaxf(v3, 0.f);
            }
            *(float2*)(Cp + (long long)row0*N + col)     = make_float2(v0, v1);
            *(float2*)(Cp + (long long)(row0+8)*N + col) = make_float2(v2, v3);
        }
    }
}

// ---------------- attention: one block per (b, n, h), 256 threads ----------------
// Q [B,Lq,N,D], K/V [B,Lk,N,D]; head h = cols h*16..h*16+15. Softmax over Lk.
// smem rows padded to 20 floats for conflict-free float4 loads.
__global__ void __launch_bounds__(256) attn_kernel(
    const float* __restrict__ Q, const float* __restrict__ Kt, const float* __restrict__ V,
    float* __restrict__ O, int Lq, int Lk)
{
    __shared__ float Qs[48*20];
    __shared__ float Ks[96*20];
    __shared__ float Vs[96*20];
    __shared__ float Ss[48*96];

    int bid = blockIdx.x;
    int h = bid & 7;
    int n = (bid >> 3) & (Nn - 1);
    int b = bid >> 12;
    int tid = threadIdx.x;

    for (int i = tid; i < Lq*4; i += 256) {
        int l = i >> 2, j4 = i & 3;
        float4 v = *(const float4*)(Q + (((long long)(b*Lq + l))*Nn + n)*Dd + h*HD + j4*4);
        *(float4*)&Qs[l*20 + j4*4] = v;
    }
    for (int i = tid; i < Lk*4; i += 256) {
        int m = i >> 2, j4 = i & 3;
        long long base = (((long long)(b*Lk + m))*Nn + n)*Dd + h*HD + j4*4;
        *(float4*)&Ks[m*20 + j4*4] = *(const float4*)(Kt + base);
        *(float4*)&Vs[m*20 + j4*4] = *(const float4*)(V + base);
    }
    __syncthreads();

    const float scale = 0.25f;  // 1/sqrt(16)
    for (int i = tid; i < Lq*Lk; i += 256) {
        int l = i / Lk, m = i - l*Lk;
        const float4* q4 = (const float4*)&Qs[l*20];
        const float4* k4 = (const float4*)&Ks[m*20];
        float s = 0.f;
        #pragma unroll
        for (int jj = 0; jj < 4; jj++) {
            float4 qa = q4[jj], ka = k4[jj];
            s = fmaf(qa.x, ka.x, s);
            s = fmaf(qa.y, ka.y, s);
            s = fmaf(qa.z, ka.z, s);
            s = fmaf(qa.w, ka.w, s);
        }
        Ss[l*Lk + m] = s * scale;
    }
    __syncthreads();

    if (tid < Lq) {
        float4* srow = (float4*)&Ss[tid*Lk];
        int n4 = Lk >> 2;
        float mx = -1e30f;
        for (int m = 0; m < n4; m++) {
            float4 s4 = srow[m];
            mx = fmaxf(mx, fmaxf(fmaxf(s4.x, s4.y), fmaxf(s4.z, s4.w)));
        }
        float sum = 0.f;
        for (int m = 0; m < n4; m++) {
            float4 s4 = srow[m];
            s4.x = __expf(s4.x - mx); s4.y = __expf(s4.y - mx);
            s4.z = __expf(s4.z - mx); s4.w = __expf(s4.w - mx);
            sum += s4.x + s4.y + s4.z + s4.w;
            srow[m] = s4;
        }
        float inv = 1.f / sum;
        for (int m = 0; m < n4; m++) {
            float4 s4 = srow[m];
            s4.x *= inv; s4.y *= inv; s4.z *= inv; s4.w *= inv;
            srow[m] = s4;
        }
    }
    __syncthreads();

    for (int i = tid; i < Lq*4; i += 256) {
        int l = i >> 2, j4 = i & 3;
        const float* srow = &Ss[l*Lk];
        float4 a = make_float4(0.f, 0.f, 0.f, 0.f);
        #pragma unroll 4
        for (int m = 0; m < Lk; m++) {
            float w = srow[m];
            float4 v = *(const float4*)&Vs[m*20 + j4*4];
            a.x = fmaf(w, v.x, a.x);
            a.y = fmaf(w, v.y, a.y);
            a.z = fmaf(w, v.z, a.z);
            a.w = fmaf(w, v.w, a.w);
        }
        *(float4*)(O + (((long long)(b*Lq + l))*Nn + n)*Dd + h*HD + j4*4) = a;
    }
}

// ---------------- fused residual add + LayerNorm (1 warp per 128-elem row) ----------------
__global__ void __launch_bounds__(256) ln_add_kernel(
    float* __restrict__ out, const float* __restrict__ X, const float* __restrict__ P,
    const float* __restrict__ g, const float* __restrict__ bta, int rows)
{
    int row  = (blockIdx.x * 256 + threadIdx.x) >> 5;
    int lane = threadIdx.x & 31;
    if (row >= rows) return;
    long long base = (long long)row * Dd + lane*4;
    float4 a = *(const float4*)(X + base);
    float4 p = *(const float4*)(P + base);
    float v0 = a.x+p.x, v1 = a.y+p.y, v2 = a.z+p.z, v3 = a.w+p.w;
    float s  = v0+v1+v2+v3;
    float s2 = v0*v0+v1*v1+v2*v2+v3*v3;
    #pragma unroll
    for (int o = 16; o; o >>= 1) {
        s  += __shfl_xor_sync(0xffffffffu, s,  o);
        s2 += __shfl_xor_sync(0xffffffffu, s2, o);
    }
    float mu  = s * (1.f/128.f);
    float var = s2 * (1.f/128.f) - mu*mu;
    float rs  = rsqrtf(var + 1e-5f);
    float4 gg = *(const float4*)(g   + lane*4);
    float4 bb = *(const float4*)(bta + lane*4);
    float4 o4;
    o4.x = (v0-mu)*rs*gg.x + bb.x;
    o4.y = (v1-mu)*rs*gg.y + bb.y;
    o4.z = (v2-mu)*rs*gg.z + bb.z;
    o4.w = (v3-mu)*rs*gg.w + bb.w;
    *(float4*)(out + base) = o4;
}

// ---------------- transpose data[b,l] ([512,128]) -> g0 rows of Hc ([128,512]) ----------------
__global__ void transpose_g0_kernel(const float* __restrict__ in, float* __restrict__ out)
{
    __shared__ float t[32][33];
    int bl = blockIdx.z;
    int n0 = blockIdx.x * 32;
    int c0 = blockIdx.y * 32;
    const float* ip = in  + (long long)bl * (Nn*Dd);
    float*       op = out + (long long)bl * (640*Nn);
    #pragma unroll
    for (int j = 0; j < 32; j += 8)
        t[threadIdx.y + j][threadIdx.x] = ip[(n0 + threadIdx.y + j)*Dd + c0 + threadIdx.x];
    __syncthreads();
    #pragma unroll
    for (int j = 0; j < 32; j += 8)
        op[(c0 + threadIdx.y + j)*Nn + n0 + threadIdx.x] = t[threadIdx.x][threadIdx.y + j];
}

// ---------------- transpose gout[bl] ([128,512]) + gcn_b -> dts ([512,128]) ----------------
__global__ void transpose_gout_kernel(const float* __restrict__ in, const float* __restrict__ gb,
                                      float* __restrict__ out)
{
    __shared__ float t[32][33];
    int bl = blockIdx.z;
    int l  = bl % Ll;
    int n0 = blockIdx.x * 32;
    int o0 = blockIdx.y * 32;
    const float* ip = in  + (long long)bl * (Dd*Nn);
    float*       op = out + (long long)bl * (Nn*Dd);
    #pragma unroll
    for (int j = 0; j < 32; j += 8)
        t[threadIdx.y + j][threadIdx.x] = ip[(o0 + threadIdx.y + j)*Nn + n0 + threadIdx.x];
    __syncthreads();
    #pragma unroll
    for (int j = 0; j < 32; j += 8) {
        int o = o0 + threadIdx.x;
        op[(n0 + threadIdx.y + j)*Dd + o] = t[threadIdx.x][threadIdx.y + j] + gb[l*Dd + o];
    }
}

// ---------------- host ----------------
static inline void gemm(const float* A, const float* B, float* C, int M, int N, int K,
                        long long sA, long long sB, long long sC, int batch, int modA,
                        const float* bias, int relu)
{
    dim3 grid(N/128, M/128, batch);
    sgemm_kernel<<<grid, 256>>>(A, B, C, M, N, K, sA, sB, sC, modA, bias, relu);
}

extern "C" void kernel_launch(void* const* d_in, const int* in_sizes, int n_in,
                              void* d_out, int out_size)
{
    const float* x       = (const float*)d_in[0];
    const float* memory  = (const float*)d_in[1];
    const float* data    = (const float*)d_in[2];
    const float* support = (const float*)d_in[3];
    const float* Wq_s = (const float*)d_in[4];
    const float* Wk_s = (const float*)d_in[5];
    const float* Wv_s = (const float*)d_in[6];
    const float* Wo_s = (const float*)d_in[7];
    const float* Wq_c = (const float*)d_in[8];
    const float* Wk_c = (const float*)d_in[9];
    const float* Wv_c = (const float*)d_in[10];
    const float* Wo_c = (const float*)d_in[11];
    const float* W1   = (const float*)d_in[12];
    const float* b1   = (const float*)d_in[13];
    const float* W2   = (const float*)d_in[14];
    const float* b2   = (const float*)d_in[15];
    const float* W3   = (const float*)d_in[16];
    const float* b3   = (const float*)d_in[17];
    const float* gcnW = (const float*)d_in[18];
    const float* gcnB = (const float*)d_in[19];
    const float* ln1g = (const float*)d_in[20];
    const float* ln1b = (const float*)d_in[21];
    const float* ln2g = (const float*)d_in[22];
    const float* ln2b = (const float*)d_in[23];
    const float* ln3g = (const float*)d_in[24];
    const float* ln3b = (const float*)d_in[25];

    float *q, *k, *v, *t, *h, *xn, *y, *big, *Hb, *go;
    cudaGetSymbolAddress((void**)&q,  g_q);
    cudaGetSymbolAddress((void**)&k,  g_k);
    cudaGetSymbolAddress((void**)&v,  g_v);
    cudaGetSymbolAddress((void**)&t,  g_t);
    cudaGetSymbolAddress((void**)&h,  g_h);
    cudaGetSymbolAddress((void**)&xn, g_xn);
    cudaGetSymbolAddress((void**)&y,  g_y);
    cudaGetSymbolAddress((void**)&big, g_big);
    cudaGetSymbolAddress((void**)&Hb, g_Hb);
    cudaGetSymbolAddress((void**)&go, g_go);

    float* out1 = (float*)d_out;               // LN3(xn + y)
    float* out2 = out1 + (long long)M1 * Dd;   // dts

    const int nLnBlocks = M1 / 8;              // 8 rows per 256-thr block

    // ---- self-attention ----
    gemm(x, Wq_s, q, M1, Dd, Dd, 0,0,0, 1,0, nullptr, 0);
    gemm(x, Wk_s, k, M1, Dd, Dd, 0,0,0, 1,0, nullptr, 0);
    gemm(x, Wv_s, v, M1, Dd, Dd, 0,0,0, 1,0, nullptr, 0);
    attn_kernel<<<Bb*Nn*Hh, 256>>>(q, k, v, t, Ll, Ll);
    gemm(t, Wo_s, q, M1, Dd, Dd, 0,0,0, 1,0, nullptr, 0);
    ln_add_kernel<<<nLnBlocks, 256>>>(h, x, q, ln1g, ln1b, M1);

    // ---- cross-attention ----
    gemm(h,      Wq_c, t, M1, Dd, Dd, 0,0,0, 1,0, nullptr, 0);
    gemm(memory, Wk_c, k, M2, Dd, Dd, 0,0,0, 1,0, nullptr, 0);
    gemm(memory, Wv_c, v, M2, Dd, Dd, 0,0,0, 1,0, nullptr, 0);
    attn_kernel<<<Bb*Nn*Hh, 256>>>(t, k, v, q, Ll, LP);
    gemm(q, Wo_c, t, M1, Dd, Dd, 0,0,0, 1,0, nullptr, 0);
    ln_add_kernel<<<nLnBlocks, 256>>>(xn, h, t, ln2g, ln2b, M1);

    // ---- FFN ----
    gemm(xn,  W1, big, M1, DF, Dd, 0,0,0, 1,0, b1, 1);   // relu(xn@W1+b1)
    gemm(big, W2, y,   M1, Dd, DF, 0,0,0, 1,0, b2, 0);   // y
    ln_add_kernel<<<nLnBlocks, 256>>>(out1, xn, y, ln3g, ln3b, M1);  // output 1

    // ---- dynamic adjacency A = y@W3 + b3  ([192][512][512] in g_big) ----
    gemm(y, W3, big, M1, Nn, Dd, 0,0,0, 1,0, b3, 0);

    // ---- GCN ----
    transpose_g0_kernel<<<dim3(16,4,BLn), dim3(32,8)>>>(data, Hb);   // g0 -> rows 0..127
    // s1 = g0@S         -> rows 128..255
    gemm(Hb,              support, Hb +  65536, 128, Nn, Nn, 327680LL, 0,        327680LL, BLn, 0, nullptr, 0);
    // d1 = g0@A[bl]     -> rows 384..511
    gemm(Hb,              big,     Hb + 196608, 128, Nn, Nn, 327680LL, 262144LL, 327680LL, BLn, 0, nullptr, 0);
    // s2 = s1@S         -> rows 256..383
    gemm(Hb +  65536,     support, Hb + 131072, 128, Nn, Nn, 327680LL, 0,        327680LL, BLn, 0, nullptr, 0);
    // d2 = d1@A[bl]     -> rows 512..639
    gemm(Hb + 196608,     big,     Hb + 262144, 128, Nn, Nn, 327680LL, 262144LL, 327680LL, BLn, 0, nullptr, 0);
    // gout[bl] = gcn_W[l] @ Hc[bl]   (K = 640)
    gemm(gcnW, Hb, go, 128, Nn, 5*Dd, 81920LL, 327680LL, 65536LL, BLn, Ll, nullptr, 0);
    // dts = gout^T + gcn_b  -> output 2
    transpose_gout_kernel<<<dim3(16,4,BLn), dim3(32,8)>>>(go, gcnB, out2);
}